// round 7
// baseline (speedup 1.0000x reference)
#include <cuda_runtime.h>
#include <cuda_bf16.h>
#include <cstdint>

#define LL 2048
#define DD 1024
#define GDIM 256

typedef __nv_bfloat16 bf16;
typedef __nv_bfloat162 bf162;

// Scratch (device globals; allocation in kernel_launch is forbidden)
__device__ bf16  g_xb [LL*DD];
__device__ bf16  g_wq [DD*DD];
__device__ bf16  g_wkv[2*DD*DD];
__device__ bf16  g_wo [DD*DD];
__device__ bf16  g_q  [LL*DD];        // Q bf16, pre-scaled by 1/8
__device__ bf16  g_kb [4*LL*GDIM];    // K per group [G][L][256]
__device__ bf16  g_vb [4*LL*GDIM];    // V per group [G][L][256]
__device__ bf16  g_s  [16u*LL*LL];    // scores/probs bf16, 16 slots (134 MB)
__device__ float g_of4[4u*LL*DD];     // per-G fp32 partials of O (32 MB)
__device__ bf16  g_ob [LL*DD];        // attention output bf16
__device__ float g_y  [LL*DD];        // pre-LN residual fp32

// ---------------------------------------------------------------------------
// PTX wrappers
// ---------------------------------------------------------------------------
__device__ __forceinline__ void ldsm4(uint32_t* r, const bf16* p) {
    uint32_t a = (uint32_t)__cvta_generic_to_shared(p);
    asm volatile("ldmatrix.sync.aligned.m8n8.x4.shared.b16 {%0,%1,%2,%3}, [%4];"
                 : "=r"(r[0]), "=r"(r[1]), "=r"(r[2]), "=r"(r[3]) : "r"(a));
}
__device__ __forceinline__ void ldsm4t(uint32_t* r, const bf16* p) {
    uint32_t a = (uint32_t)__cvta_generic_to_shared(p);
    asm volatile("ldmatrix.sync.aligned.m8n8.x4.trans.shared.b16 {%0,%1,%2,%3}, [%4];"
                 : "=r"(r[0]), "=r"(r[1]), "=r"(r[2]), "=r"(r[3]) : "r"(a));
}
__device__ __forceinline__ void mma16816(float* c, const uint32_t* a,
                                         uint32_t b0, uint32_t b1) {
    asm volatile("mma.sync.aligned.m16n8k16.row.col.f32.bf16.bf16.f32 "
                 "{%0,%1,%2,%3}, {%4,%5,%6,%7}, {%8,%9}, {%0,%1,%2,%3};"
                 : "+f"(c[0]), "+f"(c[1]), "+f"(c[2]), "+f"(c[3])
                 : "r"(a[0]), "r"(a[1]), "r"(a[2]), "r"(a[3]), "r"(b0), "r"(b1));
}
__device__ __forceinline__ void cp16(bf16* dst, const bf16* src) {
    uint32_t d = (uint32_t)__cvta_generic_to_shared(dst);
    asm volatile("cp.async.cg.shared.global [%0], [%1], 16;" :: "r"(d), "l"(src) : "memory");
}
__device__ __forceinline__ void cp_commit() {
    asm volatile("cp.async.commit_group;" ::: "memory");
}
template<int N>
__device__ __forceinline__ void cp_wait() {
    asm volatile("cp.async.wait_group %0;" :: "n"(N) : "memory");
}
__device__ __forceinline__ bf162 pack2(float a, float b) {
    bf162 r; r.x = __float2bfloat16_rn(a); r.y = __float2bfloat16_rn(b); return r;
}

// ---------------------------------------------------------------------------
// Fused input conversion: blockIdx.y selects segment (x, Wq, Wkv, Wo).
// ---------------------------------------------------------------------------
__global__ __launch_bounds__(256)
void cvt_all_k(const float* __restrict__ x,  const float* __restrict__ Wq,
               const float* __restrict__ Wkv, const float* __restrict__ Wo)
{
    const float* src; bf16* dst; int n;
    switch (blockIdx.y) {
        case 0: src = x;   dst = g_xb;  n = LL*DD;   break;
        case 1: src = Wq;  dst = g_wq;  n = DD*DD;   break;
        case 2: src = Wkv; dst = g_wkv; n = 2*DD*DD; break;
        default:src = Wo;  dst = g_wo;  n = DD*DD;   break;
    }
    const int i = (blockIdx.x * 256 + threadIdx.x) * 4;
    if (i < n) {
        float4 v = *(const float4*)(src + i);
        *(bf162*)(dst + i)     = pack2(v.x, v.y);
        *(bf162*)(dst + i + 2) = pack2(v.z, v.w);
    }
}

// Sum the 4 per-G fp32 partials -> bf16 O
__global__ __launch_bounds__(256)
void cvt_o_k()
{
    const int i = (blockIdx.x * 256 + threadIdx.x) * 4;
    float4 a = *(const float4*)(g_of4 + i);
    float4 b = *(const float4*)(g_of4 + (size_t)LL*DD + i);
    float4 c = *(const float4*)(g_of4 + 2u*(size_t)LL*DD + i);
    float4 d = *(const float4*)(g_of4 + 3u*(size_t)LL*DD + i);
    *(bf162*)(g_ob + i)     = pack2(a.x+b.x+c.x+d.x, a.y+b.y+c.y+d.y);
    *(bf162*)(g_ob + i + 2) = pack2(a.z+b.z+c.z+d.z, a.w+b.w+c.w+d.w);
}

// ---------------------------------------------------------------------------
// bf16 tensor-core GEMM, cp.async 3-stage pipeline, BK=64, dynamic smem.
// 128x128x64 stages, 8 warps (4m x 2n), warp tile 32x64, mma.sync m16n8k16.
// MODE 0: Q = x@Wq^T * 0.125       -> g_q
// MODE 1: KV = x@Wkv^T, scatter    -> g_kb/g_vb
// MODE 2: S = Q_g @ K_G^T ; bz = slot = g*4+G -> g_s
// MODE 3: partial O: P_slot @ V_G ; bz = slot; out -> g_of4[G] (fp32)
// MODE 4: Y = x + O@Wo^T           -> g_y
// ---------------------------------------------------------------------------
template<int MODE>
__global__ __launch_bounds__(256, 2)
void gemm_tc(const float* __restrict__ P0)
{
    constexpr int BM = 128, BN = 128, BK = 64;
    constexpr int SA  = 72;                        // A / k-major B row stride
    constexpr int SBR = (MODE == 3) ? BK : BN;
    constexpr int SBS = (MODE == 3) ? 136 : 72;
    constexpr int ASZ = BM * SA, BSZ = SBR * SBS;
    extern __shared__ bf16 dsm[];
    bf16* Asb = dsm;
    bf16* Bsb = dsm + 3 * ASZ;

    const int tid = threadIdx.x, lane = tid & 31, w = tid >> 5;
    const int wm = w & 3, wn = w >> 2;
    const int bx = blockIdx.x, by = blockIdx.y, bz = blockIdx.z;

    float acc[2][8][4];
    #pragma unroll
    for (int i = 0; i < 2; i++)
        #pragma unroll
        for (int j = 0; j < 8; j++)
            #pragma unroll
            for (int k = 0; k < 4; k++) acc[i][j][k] = 0.f;

    const bf16* Ab; const bf16* Bb; int lda, ldb, Ks;
    if constexpr (MODE == 0) {
        Ab = g_xb; Bb = g_wq;  lda = DD; ldb = DD; Ks = DD;
    } else if constexpr (MODE == 1) {
        Ab = g_xb; Bb = g_wkv; lda = DD; ldb = DD; Ks = DD;
    } else if constexpr (MODE == 2) {
        const int g = bz >> 2, G = bz & 3;
        Ab = g_q + g * GDIM;               lda = DD;   Ks = GDIM;
        Bb = g_kb + (size_t)G * LL * GDIM; ldb = GDIM;
    } else if constexpr (MODE == 3) {
        const int G = bz & 3;
        Ab = g_s + (size_t)bz * LL * LL;   lda = LL;   Ks = LL;
        Bb = g_vb + (size_t)G * LL * GDIM; ldb = GDIM;
    } else {
        Ab = g_ob; Bb = g_wo; lda = DD; ldb = DD; Ks = DD;
    }

    // stage loader (cp.async), BK=64: each thread stages 32 k-elems per operand
    auto stage = [&](int buf, int k0) {
        bf16* As = Asb + buf * ASZ;
        bf16* Bs = Bsb + buf * BSZ;
        {
            const int sr = tid >> 1, sc = (tid & 1) * 32;
            const bf16* ap = Ab + (size_t)(by * BM + sr) * lda + k0 + sc;
            bf16* as = &As[sr * SA + sc];
            cp16(as, ap); cp16(as + 8, ap + 8);
            cp16(as + 16, ap + 16); cp16(as + 24, ap + 24);
        }
        if constexpr (MODE != 3) {
            const int sr = tid >> 1, sc = (tid & 1) * 32;
            const bf16* bp = Bb + (size_t)(bx * BN + sr) * ldb + k0 + sc;
            bf16* bs = &Bs[sr * SBS + sc];
            cp16(bs, bp); cp16(bs + 8, bp + 8);
            cp16(bs + 16, bp + 16); cp16(bs + 24, bp + 24);
        } else {
            // [k=64][n=128] tile, n-contiguous rows; 4 thr/row x 32 cols
            const int sr = tid >> 2, sc = (tid & 3) * 32;
            const bf16* bp = Bb + (size_t)(k0 + sr) * ldb + bx * BN + sc;
            bf16* bs = &Bs[sr * SBS + sc];
            cp16(bs, bp); cp16(bs + 8, bp + 8);
            cp16(bs + 16, bp + 16); cp16(bs + 24, bp + 24);
        }
        cp_commit();
    };

    const int nk = Ks / BK;
    stage(0, 0);
    stage(1, BK);
    for (int ki = 0; ki < nk; ki++) {
        const int buf = ki % 3;
        if (ki == nk - 1) cp_wait<0>(); else cp_wait<1>();
        __syncthreads();
        if (ki + 2 < nk) stage((ki + 2) % 3, (ki + 2) * BK);

        const bf16* As = Asb + buf * ASZ;
        const bf16* Bs = Bsb + buf * BSZ;
        #pragma unroll
        for (int ks = 0; ks < 4; ks++) {
            uint32_t ah[2][4];
            const int ar = wm * 32 + (lane & 15);
            const int ac = ks * 16 + (lane >> 4) * 8;
            #pragma unroll
            for (int mt = 0; mt < 2; mt++)
                ldsm4(ah[mt], &As[(ar + mt * 16) * SA + ac]);
            #pragma unroll
            for (int ntp = 0; ntp < 4; ntp++) {
                uint32_t bh[4];
                uint32_t b0, b1, c0, c1;
                if constexpr (MODE != 3) {
                    const int br = wn * 64 + ntp * 16 + (lane & 15);
                    const int bc = ks * 16 + (lane >> 4) * 8;
                    ldsm4(bh, &Bs[br * SBS + bc]);
                    b0 = bh[0]; b1 = bh[2]; c0 = bh[1]; c1 = bh[3];
                } else {
                    const int br = ks * 16 + (lane & 15);
                    const int bc = wn * 64 + ntp * 16 + (lane >> 4) * 8;
                    ldsm4t(bh, &Bs[br * SBS + bc]);
                    b0 = bh[0]; b1 = bh[1]; c0 = bh[2]; c1 = bh[3];
                }
                #pragma unroll
                for (int mt = 0; mt < 2; mt++) {
                    mma16816(acc[mt][2*ntp],   ah[mt], b0, b1);
                    mma16816(acc[mt][2*ntp+1], ah[mt], c0, c1);
                }
            }
        }
        __syncthreads();
    }

    // ---- epilogue ----
    const int er = lane >> 2, ec = 2 * (lane & 3);
    #pragma unroll
    for (int mt = 0; mt < 2; mt++) {
        #pragma unroll
        for (int nt = 0; nt < 8; nt++) {
            #pragma unroll
            for (int q2 = 0; q2 < 2; q2++) {
                const int m  = by * BM + wm * 32 + mt * 16 + er + q2 * 8;
                const int n0 = bx * BN + wn * 64 + nt * 8 + ec;
                const float v0 = acc[mt][nt][2*q2], v1 = acc[mt][nt][2*q2+1];
                if constexpr (MODE == 0) {
                    *(bf162*)&g_q[(size_t)m * DD + n0] = pack2(v0*0.125f, v1*0.125f);
                } else if constexpr (MODE == 1) {
                    const int head = n0 >> 7, rem = n0 & 127;
                    const int g2 = head >> 2, h = head & 3;
                    if (rem < 64)
                        *(bf162*)&g_kb[((size_t)g2*LL + m)*GDIM + h*64 + rem] = pack2(v0, v1);
                    else
                        *(bf162*)&g_vb[((size_t)g2*LL + m)*GDIM + h*64 + rem - 64] = pack2(v0, v1);
                } else if constexpr (MODE == 2) {
                    *(bf162*)&g_s[(size_t)bz*LL*LL + (size_t)m*LL + n0] = pack2(v0, v1);
                } else if constexpr (MODE == 3) {
                    const int g = bz >> 2, G = bz & 3;
                    float* dst = g_of4 + (size_t)G*LL*DD + (size_t)m*DD + g*GDIM + n0;
                    dst[0] = v0; dst[1] = v1;
                } else {
                    g_y[(size_t)m*DD + n0]     = v0 + P0[(size_t)m*DD + n0];
                    g_y[(size_t)m*DD + n0 + 1] = v1 + P0[(size_t)m*DD + n0 + 1];
                }
            }
        }
    }
}

// ---------------------------------------------------------------------------
// Row softmax over bf16 g_s, in place. One CTA per row; grid = 16*LL.
// ---------------------------------------------------------------------------
__global__ __launch_bounds__(256)
void softmax_k()
{
    bf16* S = g_s + (size_t)blockIdx.x * LL;
    const int tid = threadIdx.x;
    __shared__ float sh[8];
    uint4 raw = *(const uint4*)(S + tid * 8);
    const bf162* p2 = (const bf162*)&raw;
    float v[8];
    #pragma unroll
    for (int i = 0; i < 4; i++) {
        float2 f = __bfloat1622float2(p2[i]);
        v[2*i] = f.x; v[2*i+1] = f.y;
    }
    float m = -1e30f;
    #pragma unroll
    for (int i = 0; i < 8; i++) m = fmaxf(m, v[i]);
    #pragma unroll
    for (int o = 16; o > 0; o >>= 1) m = fmaxf(m, __shfl_xor_sync(0xffffffffu, m, o));
    if ((tid & 31) == 0) sh[tid >> 5] = m;
    __syncthreads();
    float tm = sh[0];
    #pragma unroll
    for (int w = 1; w < 8; w++) tm = fmaxf(tm, sh[w]);
    __syncthreads();
    float s = 0.f;
    #pragma unroll
    for (int i = 0; i < 8; i++) { v[i] = __expf(v[i] - tm); s += v[i]; }
    #pragma unroll
    for (int o = 16; o > 0; o >>= 1) s += __shfl_xor_sync(0xffffffffu, s, o);
    if ((tid & 31) == 0) sh[tid >> 5] = s;
    __syncthreads();
    float tot = 0.f;
    #pragma unroll
    for (int w = 0; w < 8; w++) tot += sh[w];
    const float inv = 1.0f / tot;
    uint4 out;
    bf162* o2 = (bf162*)&out;
    #pragma unroll
    for (int i = 0; i < 4; i++) o2[i] = pack2(v[2*i] * inv, v[2*i+1] * inv);
    *(uint4*)(S + tid * 8) = out;
}

// ---------------------------------------------------------------------------
// LayerNorm over g_y rows -> out. One CTA per row.
// ---------------------------------------------------------------------------
__global__ __launch_bounds__(256)
void ln_k(const float* __restrict__ gamma, const float* __restrict__ beta,
          float* __restrict__ out)
{
    const int row = blockIdx.x;
    const float* y = g_y + (size_t)row * DD;
    const int tid = threadIdx.x;
    __shared__ float sh[8];
    float v[4]; float s = 0.f;
    #pragma unroll
    for (int i = 0; i < 4; i++) { v[i] = y[tid + i * 256]; s += v[i]; }
    #pragma unroll
    for (int o = 16; o > 0; o >>= 1) s += __shfl_xor_sync(0xffffffffu, s, o);
    if ((tid & 31) == 0) sh[tid >> 5] = s;
    __syncthreads();
    float tot = 0.f;
    #pragma unroll
    for (int w = 0; w < 8; w++) tot += sh[w];
    const float mu = tot * (1.0f / 1024.0f);
    __syncthreads();
    float s2 = 0.f;
    #pragma unroll
    for (int i = 0; i < 4; i++) { const float d = v[i] - mu; s2 += d * d; }
    #pragma unroll
    for (int o = 16; o > 0; o >>= 1) s2 += __shfl_xor_sync(0xffffffffu, s2, o);
    if ((tid & 31) == 0) sh[tid >> 5] = s2;
    __syncthreads();
    float tot2 = 0.f;
    #pragma unroll
    for (int w = 0; w < 8; w++) tot2 += sh[w];
    const float r = rsqrtf(tot2 * (1.0f / 1024.0f) + 1e-5f);
    #pragma unroll
    for (int i = 0; i < 4; i++) {
        const int c = tid + i * 256;
        out[(size_t)row * DD + c] = gamma[c] * (v[i] - mu) * r + beta[c];
    }
}

extern "C" void kernel_launch(void* const* d_in, const int* in_sizes, int n_in,
                              void* d_out, int out_size)
{
    const float* x     = (const float*)d_in[0];
    const float* Wq    = (const float*)d_in[1];
    const float* Wkv   = (const float*)d_in[2];
    const float* Wo    = (const float*)d_in[3];
    const float* gamma = (const float*)d_in[4];
    const float* beta  = (const float*)d_in[5];
    float* out = (float*)d_out;
    (void)in_sizes; (void)n_in; (void)out_size;

    // dynamic smem sizes (3-stage, BK=64)
    const int smemAB = 3 * (128*72 + 128*72) * 2;   // modes 0,1,2,4: 110592 B
    const int smemM3 = 3 * (128*72 +  64*136) * 2;  // mode 3:        107520 B
    static bool attr_done = false;
    if (!attr_done) {
        cudaFuncSetAttribute(gemm_tc<0>, cudaFuncAttributeMaxDynamicSharedMemorySize, smemAB);
        cudaFuncSetAttribute(gemm_tc<1>, cudaFuncAttributeMaxDynamicSharedMemorySize, smemAB);
        cudaFuncSetAttribute(gemm_tc<2>, cudaFuncAttributeMaxDynamicSharedMemorySize, smemAB);
        cudaFuncSetAttribute(gemm_tc<3>, cudaFuncAttributeMaxDynamicSharedMemorySize, smemM3);
        cudaFuncSetAttribute(gemm_tc<4>, cudaFuncAttributeMaxDynamicSharedMemorySize, smemAB);
        attr_done = true;
    }

    dim3 blk(256);
    cvt_all_k<<<dim3(2048, 4), blk>>>(x, Wq, Wkv, Wo);        // all input cvts

    gemm_tc<0><<<dim3( 8, 16    ), blk, smemAB>>>(nullptr);   // Q proj (scaled)
    gemm_tc<1><<<dim3(16, 16    ), blk, smemAB>>>(nullptr);   // KV proj + scatter
    gemm_tc<2><<<dim3(16, 16, 16), blk, smemAB>>>(nullptr);   // 16 (g,G) score GEMMs
    softmax_k<<<16 * LL, blk>>>();                            // row softmax
    gemm_tc<3><<<dim3( 2, 16, 16), blk, smemM3>>>(nullptr);   // per-G partial O (fp32)
    cvt_o_k<<<LL*DD/1024, blk>>>();                           // sum partials -> bf16 O
    gemm_tc<4><<<dim3( 8, 16    ), blk, smemAB>>>(x);         // Y = x + O@Wo^T
    ln_k<<<LL, blk>>>(gamma, beta, out);                      // LayerNorm -> out
}

// round 10
// speedup vs baseline: 1.1236x; 1.1236x over previous
#include <cuda_runtime.h>
#include <cuda_bf16.h>
#include <cstdint>

#define LL 2048
#define DD 1024
#define GDIM 256

typedef __nv_bfloat16 bf16;
typedef __nv_bfloat162 bf162;

// Scratch (device globals; allocation in kernel_launch is forbidden)
__device__ bf16  g_xb [LL*DD];
__device__ bf16  g_wq [DD*DD];
__device__ bf16  g_wkv[2*DD*DD];
__device__ bf16  g_wo [DD*DD];
__device__ bf16  g_q  [LL*DD];        // Q bf16, pre-scaled by 1/8
__device__ bf16  g_kb [4*LL*GDIM];    // K per group [G][L][256]
__device__ bf16  g_vb [4*LL*GDIM];    // V per group [G][L][256]
__device__ bf16  g_s  [16u*LL*LL];    // scores/probs bf16, 16 slots (134 MB)
__device__ float g_of4[4u*LL*DD];     // per-G fp32 partials of O (32 MB)
__device__ bf16  g_ob [LL*DD];        // attention output bf16
__device__ float g_y  [LL*DD];        // pre-LN residual fp32

// ---------------------------------------------------------------------------
// PTX wrappers
// ---------------------------------------------------------------------------
__device__ __forceinline__ void ldsm4(uint32_t* r, const bf16* p) {
    uint32_t a = (uint32_t)__cvta_generic_to_shared(p);
    asm volatile("ldmatrix.sync.aligned.m8n8.x4.shared.b16 {%0,%1,%2,%3}, [%4];"
                 : "=r"(r[0]), "=r"(r[1]), "=r"(r[2]), "=r"(r[3]) : "r"(a));
}
__device__ __forceinline__ void ldsm4t(uint32_t* r, const bf16* p) {
    uint32_t a = (uint32_t)__cvta_generic_to_shared(p);
    asm volatile("ldmatrix.sync.aligned.m8n8.x4.trans.shared.b16 {%0,%1,%2,%3}, [%4];"
                 : "=r"(r[0]), "=r"(r[1]), "=r"(r[2]), "=r"(r[3]) : "r"(a));
}
__device__ __forceinline__ void mma16816(float* c, const uint32_t* a,
                                         uint32_t b0, uint32_t b1) {
    asm volatile("mma.sync.aligned.m16n8k16.row.col.f32.bf16.bf16.f32 "
                 "{%0,%1,%2,%3}, {%4,%5,%6,%7}, {%8,%9}, {%0,%1,%2,%3};"
                 : "+f"(c[0]), "+f"(c[1]), "+f"(c[2]), "+f"(c[3])
                 : "r"(a[0]), "r"(a[1]), "r"(a[2]), "r"(a[3]), "r"(b0), "r"(b1));
}
__device__ __forceinline__ void cp16(bf16* dst, const bf16* src) {
    uint32_t d = (uint32_t)__cvta_generic_to_shared(dst);
    asm volatile("cp.async.cg.shared.global [%0], [%1], 16;" :: "r"(d), "l"(src) : "memory");
}
__device__ __forceinline__ void cp_commit() {
    asm volatile("cp.async.commit_group;" ::: "memory");
}
template<int N>
__device__ __forceinline__ void cp_wait() {
    asm volatile("cp.async.wait_group %0;" :: "n"(N) : "memory");
}
__device__ __forceinline__ bf162 pack2(float a, float b) {
    bf162 r; r.x = __float2bfloat16_rn(a); r.y = __float2bfloat16_rn(b); return r;
}

// ---------------------------------------------------------------------------
// Fused input conversion: blockIdx.y selects segment (x, Wq, Wkv, Wo).
// ---------------------------------------------------------------------------
__global__ __launch_bounds__(256)
void cvt_all_k(const float* __restrict__ x,  const float* __restrict__ Wq,
               const float* __restrict__ Wkv, const float* __restrict__ Wo)
{
    const float* src; bf16* dst; int n;
    switch (blockIdx.y) {
        case 0: src = x;   dst = g_xb;  n = LL*DD;   break;
        case 1: src = Wq;  dst = g_wq;  n = DD*DD;   break;
        case 2: src = Wkv; dst = g_wkv; n = 2*DD*DD; break;
        default:src = Wo;  dst = g_wo;  n = DD*DD;   break;
    }
    const int i = (blockIdx.x * 256 + threadIdx.x) * 4;
    if (i < n) {
        float4 v = *(const float4*)(src + i);
        *(bf162*)(dst + i)     = pack2(v.x, v.y);
        *(bf162*)(dst + i + 2) = pack2(v.z, v.w);
    }
}

// Sum the 4 per-G fp32 partials -> bf16 O
__global__ __launch_bounds__(256)
void cvt_o_k()
{
    const int i = (blockIdx.x * 256 + threadIdx.x) * 4;
    float4 a = *(const float4*)(g_of4 + i);
    float4 b = *(const float4*)(g_of4 + (size_t)LL*DD + i);
    float4 c = *(const float4*)(g_of4 + 2u*(size_t)LL*DD + i);
    float4 d = *(const float4*)(g_of4 + 3u*(size_t)LL*DD + i);
    *(bf162*)(g_ob + i)     = pack2(a.x+b.x+c.x+d.x, a.y+b.y+c.y+d.y);
    *(bf162*)(g_ob + i + 2) = pack2(a.z+b.z+c.z+d.z, a.w+b.w+c.w+d.w);
}

// ---------------------------------------------------------------------------
// bf16 tensor-core GEMM, cp.async 4-stage pipeline, ONE barrier per k-iter.
// 128x128x32 stages, 8 warps (4m x 2n), warp tile 32x64, mma.sync m16n8k16.
// Ledger: one commit group per iteration (stage or empty); wait_group<2> at
// iteration ki positionally guarantees chunk ki has landed. Buffer (ki+3)%4
// never collides with compute buffer ki%4; overwrite of (ki-1)%4 is fenced by
// the top-of-iteration __syncthreads.
// MODE 0: Q = x@Wq^T * 0.125       -> g_q
// MODE 1: KV = x@Wkv^T, scatter    -> g_kb/g_vb
// MODE 2: S = Q_g @ K_G^T ; bz = slot = g*4+G -> g_s
// MODE 3: partial O: P_slot @ V_G ; bz = slot; out -> g_of4[G] (fp32)
// MODE 4: Y = x + O@Wo^T           -> g_y
// ---------------------------------------------------------------------------
template<int MODE>
__global__ __launch_bounds__(256, 2)
void gemm_tc(const float* __restrict__ P0)
{
    constexpr int BM = 128, BN = 128, BK = 32;
    constexpr int SA  = 40;
    constexpr int SBR = (MODE == 3) ? BK : BN;
    constexpr int SBS = (MODE == 3) ? 136 : 40;
    constexpr int ASZ = BM * SA, BSZ = SBR * SBS;
    extern __shared__ bf16 dsm[];
    bf16* Asb = dsm;
    bf16* Bsb = dsm + 4 * ASZ;

    const int tid = threadIdx.x, lane = tid & 31, w = tid >> 5;
    const int wm = w & 3, wn = w >> 2;
    const int bx = blockIdx.x, by = blockIdx.y, bz = blockIdx.z;

    float acc[2][8][4];
    #pragma unroll
    for (int i = 0; i < 2; i++)
        #pragma unroll
        for (int j = 0; j < 8; j++)
            #pragma unroll
            for (int k = 0; k < 4; k++) acc[i][j][k] = 0.f;

    const bf16* Ab; const bf16* Bb; int lda, ldb, Ks;
    if constexpr (MODE == 0) {
        Ab = g_xb; Bb = g_wq;  lda = DD; ldb = DD; Ks = DD;
    } else if constexpr (MODE == 1) {
        Ab = g_xb; Bb = g_wkv; lda = DD; ldb = DD; Ks = DD;
    } else if constexpr (MODE == 2) {
        const int g = bz >> 2, G = bz & 3;
        Ab = g_q + g * GDIM;               lda = DD;   Ks = GDIM;
        Bb = g_kb + (size_t)G * LL * GDIM; ldb = GDIM;
    } else if constexpr (MODE == 3) {
        const int G = bz & 3;
        Ab = g_s + (size_t)bz * LL * LL;   lda = LL;   Ks = LL;
        Bb = g_vb + (size_t)G * LL * GDIM; ldb = GDIM;
    } else {
        Ab = g_ob; Bb = g_wo; lda = DD; ldb = DD; Ks = DD;
    }

    // stage chunk -> buffer (cp.async); one commit group per call
    auto stage = [&](int buf, int k0) {
        bf16* As = Asb + buf * ASZ;
        bf16* Bs = Bsb + buf * BSZ;
        {
            const int sr = tid >> 1, sc = (tid & 1) * 16;
            const bf16* ap = Ab + (size_t)(by * BM + sr) * lda + k0 + sc;
            cp16(&As[sr * SA + sc],     ap);
            cp16(&As[sr * SA + sc + 8], ap + 8);
        }
        if constexpr (MODE != 3) {
            const int sr = tid >> 1, sc = (tid & 1) * 16;
            const bf16* bp = Bb + (size_t)(bx * BN + sr) * ldb + k0 + sc;
            cp16(&Bs[sr * SBS + sc],     bp);
            cp16(&Bs[sr * SBS + sc + 8], bp + 8);
        } else {
            const int sr = tid >> 3, sc = (tid & 7) * 16;
            const bf16* bp = Bb + (size_t)(k0 + sr) * ldb + bx * BN + sc;
            cp16(&Bs[sr * SBS + sc],     bp);
            cp16(&Bs[sr * SBS + sc + 8], bp + 8);
        }
        cp_commit();
    };

    const int nk = Ks / BK;                 // 8 / 32 / 64 -- always >= 3
    stage(0, 0);
    stage(1, BK);
    stage(2, 2 * BK);
    for (int ki = 0; ki < nk; ki++) {
        cp_wait<2>();                       // positional: chunk ki landed
        __syncthreads();                    // all warps' waits done; buffers safe
        if (ki + 3 < nk) stage((ki + 3) & 3, (ki + 3) * BK);
        else cp_commit();                   // keep one group per iteration

        const bf16* As = Asb + (ki & 3) * ASZ;
        const bf16* Bs = Bsb + (ki & 3) * BSZ;
        #pragma unroll
        for (int ks = 0; ks < 2; ks++) {
            uint32_t ah[2][4];
            const int ar = wm * 32 + (lane & 15);
            const int ac = ks * 16 + (lane >> 4) * 8;
            #pragma unroll
            for (int mt = 0; mt < 2; mt++)
                ldsm4(ah[mt], &As[(ar + mt * 16) * SA + ac]);
            #pragma unroll
            for (int ntp = 0; ntp < 4; ntp++) {
                uint32_t bh[4];
                uint32_t b0, b1, c0, c1;
                if constexpr (MODE != 3) {
                    const int br = wn * 64 + ntp * 16 + (lane & 15);
                    const int bc = ks * 16 + (lane >> 4) * 8;
                    ldsm4(bh, &Bs[br * SBS + bc]);
                    b0 = bh[0]; b1 = bh[2]; c0 = bh[1]; c1 = bh[3];
                } else {
                    const int br = ks * 16 + (lane & 15);
                    const int bc = wn * 64 + ntp * 16 + (lane >> 4) * 8;
                    ldsm4t(bh, &Bs[br * SBS + bc]);
                    b0 = bh[0]; b1 = bh[1]; c0 = bh[2]; c1 = bh[3];
                }
                #pragma unroll
                for (int mt = 0; mt < 2; mt++) {
                    mma16816(acc[mt][2*ntp],   ah[mt], b0, b1);
                    mma16816(acc[mt][2*ntp+1], ah[mt], c0, c1);
                }
            }
        }
        // no trailing barrier: next iteration's __syncthreads fences reuse
    }

    // ---- epilogue ----
    const int er = lane >> 2, ec = 2 * (lane & 3);
    #pragma unroll
    for (int mt = 0; mt < 2; mt++) {
        #pragma unroll
        for (int nt = 0; nt < 8; nt++) {
            #pragma unroll
            for (int q2 = 0; q2 < 2; q2++) {
                const int m  = by * BM + wm * 32 + mt * 16 + er + q2 * 8;
                const int n0 = bx * BN + wn * 64 + nt * 8 + ec;
                const float v0 = acc[mt][nt][2*q2], v1 = acc[mt][nt][2*q2+1];
                if constexpr (MODE == 0) {
                    *(bf162*)&g_q[(size_t)m * DD + n0] = pack2(v0*0.125f, v1*0.125f);
                } else if constexpr (MODE == 1) {
                    const int head = n0 >> 7, rem = n0 & 127;
                    const int g2 = head >> 2, h = head & 3;
                    if (rem < 64)
                        *(bf162*)&g_kb[((size_t)g2*LL + m)*GDIM + h*64 + rem] = pack2(v0, v1);
                    else
                        *(bf162*)&g_vb[((size_t)g2*LL + m)*GDIM + h*64 + rem - 64] = pack2(v0, v1);
                } else if constexpr (MODE == 2) {
                    *(bf162*)&g_s[(size_t)bz*LL*LL + (size_t)m*LL + n0] = pack2(v0, v1);
                } else if constexpr (MODE == 3) {
                    const int g = bz >> 2, G = bz & 3;
                    float* dst = g_of4 + (size_t)G*LL*DD + (size_t)m*DD + g*GDIM + n0;
                    dst[0] = v0; dst[1] = v1;
                } else {
                    g_y[(size_t)m*DD + n0]     = v0 + P0[(size_t)m*DD + n0];
                    g_y[(size_t)m*DD + n0 + 1] = v1 + P0[(size_t)m*DD + n0 + 1];
                }
            }
        }
    }
}

// ---------------------------------------------------------------------------
// Row softmax over bf16 g_s, in place. One CTA per row; grid = 16*LL.
// ---------------------------------------------------------------------------
__global__ __launch_bounds__(256)
void softmax_k()
{
    bf16* S = g_s + (size_t)blockIdx.x * LL;
    const int tid = threadIdx.x;
    __shared__ float sh[8];
    uint4 raw = *(const uint4*)(S + tid * 8);
    const bf162* p2 = (const bf162*)&raw;
    float v[8];
    #pragma unroll
    for (int i = 0; i < 4; i++) {
        float2 f = __bfloat1622float2(p2[i]);
        v[2*i] = f.x; v[2*i+1] = f.y;
    }
    float m = -1e30f;
    #pragma unroll
    for (int i = 0; i < 8; i++) m = fmaxf(m, v[i]);
    #pragma unroll
    for (int o = 16; o > 0; o >>= 1) m = fmaxf(m, __shfl_xor_sync(0xffffffffu, m, o));
    if ((tid & 31) == 0) sh[tid >> 5] = m;
    __syncthreads();
    float tm = sh[0];
    #pragma unroll
    for (int w = 1; w < 8; w++) tm = fmaxf(tm, sh[w]);
    __syncthreads();
    float s = 0.f;
    #pragma unroll
    for (int i = 0; i < 8; i++) { v[i] = __expf(v[i] - tm); s += v[i]; }
    #pragma unroll
    for (int o = 16; o > 0; o >>= 1) s += __shfl_xor_sync(0xffffffffu, s, o);
    if ((tid & 31) == 0) sh[tid >> 5] = s;
    __syncthreads();
    float tot = 0.f;
    #pragma unroll
    for (int w = 0; w < 8; w++) tot += sh[w];
    const float inv = 1.0f / tot;
    uint4 out;
    bf162* o2 = (bf162*)&out;
    #pragma unroll
    for (int i = 0; i < 4; i++) o2[i] = pack2(v[2*i] * inv, v[2*i+1] * inv);
    *(uint4*)(S + tid * 8) = out;
}

// ---------------------------------------------------------------------------
// LayerNorm over g_y rows -> out. One CTA per row.
// ---------------------------------------------------------------------------
__global__ __launch_bounds__(256)
void ln_k(const float* __restrict__ gamma, const float* __restrict__ beta,
          float* __restrict__ out)
{
    const int row = blockIdx.x;
    const float* y = g_y + (size_t)row * DD;
    const int tid = threadIdx.x;
    __shared__ float sh[8];
    float v[4]; float s = 0.f;
    #pragma unroll
    for (int i = 0; i < 4; i++) { v[i] = y[tid + i * 256]; s += v[i]; }
    #pragma unroll
    for (int o = 16; o > 0; o >>= 1) s += __shfl_xor_sync(0xffffffffu, s, o);
    if ((tid & 31) == 0) sh[tid >> 5] = s;
    __syncthreads();
    float tot = 0.f;
    #pragma unroll
    for (int w = 0; w < 8; w++) tot += sh[w];
    const float mu = tot * (1.0f / 1024.0f);
    __syncthreads();
    float s2 = 0.f;
    #pragma unroll
    for (int i = 0; i < 4; i++) { const float d = v[i] - mu; s2 += d * d; }
    #pragma unroll
    for (int o = 16; o > 0; o >>= 1) s2 += __shfl_xor_sync(0xffffffffu, s2, o);
    if ((tid & 31) == 0) sh[tid >> 5] = s2;
    __syncthreads();
    float tot2 = 0.f;
    #pragma unroll
    for (int w = 0; w < 8; w++) tot2 += sh[w];
    const float r = rsqrtf(tot2 * (1.0f / 1024.0f) + 1e-5f);
    #pragma unroll
    for (int i = 0; i < 4; i++) {
        const int c = tid + i * 256;
        out[(size_t)row * DD + c] = gamma[c] * (v[i] - mu) * r + beta[c];
    }
}

extern "C" void kernel_launch(void* const* d_in, const int* in_sizes, int n_in,
                              void* d_out, int out_size)
{
    const float* x     = (const float*)d_in[0];
    const float* Wq    = (const float*)d_in[1];
    const float* Wkv   = (const float*)d_in[2];
    const float* Wo    = (const float*)d_in[3];
    const float* gamma = (const float*)d_in[4];
    const float* beta  = (const float*)d_in[5];
    float* out = (float*)d_out;
    (void)in_sizes; (void)n_in; (void)out_size;

    // dynamic smem sizes (4-stage, BK=32)
    const int smemAB = 4 * (128*40 + 128*40) * 2;   // modes 0,1,2,4: 81920 B
    const int smemM3 = 4 * (128*40 +  32*136) * 2;  // mode 3:        75776 B
    static bool attr_done = false;
    if (!attr_done) {
        cudaFuncSetAttribute(gemm_tc<0>, cudaFuncAttributeMaxDynamicSharedMemorySize, smemAB);
        cudaFuncSetAttribute(gemm_tc<1>, cudaFuncAttributeMaxDynamicSharedMemorySize, smemAB);
        cudaFuncSetAttribute(gemm_tc<2>, cudaFuncAttributeMaxDynamicSharedMemorySize, smemAB);
        cudaFuncSetAttribute(gemm_tc<3>, cudaFuncAttributeMaxDynamicSharedMemorySize, smemM3);
        cudaFuncSetAttribute(gemm_tc<4>, cudaFuncAttributeMaxDynamicSharedMemorySize, smemAB);
        attr_done = true;
    }

    dim3 blk(256);
    cvt_all_k<<<dim3(2048, 4), blk>>>(x, Wq, Wkv, Wo);        // input cvts

    gemm_tc<0><<<dim3( 8, 16    ), blk, smemAB>>>(nullptr);   // Q proj (scaled)
    gemm_tc<1><<<dim3(16, 16    ), blk, smemAB>>>(nullptr);   // KV proj + scatter
    gemm_tc<2><<<dim3(16, 16, 16), blk, smemAB>>>(nullptr);   // 16 (g,G) score GEMMs
    softmax_k<<<16 * LL, blk>>>();                            // row softmax
    gemm_tc<3><<<dim3( 2, 16, 16), blk, smemM3>>>(nullptr);   // per-slot partial O
    cvt_o_k<<<LL*DD/1024, blk>>>();                           // sum partials -> bf16 O
    gemm_tc<4><<<dim3( 8, 16    ), blk, smemAB>>>(x);         // Y = x + O@Wo^T
    ln_k<<<LL, blk>>>(gamma, beta, out);                      // LayerNorm -> out
}